// round 1
// baseline (speedup 1.0000x reference)
#include <cuda_runtime.h>
#include <math.h>

#define Bsz 32
#define Cch 128
#define Hh  64
#define Ww  64
#define OCn 128
#define En  8
#define Tn  256
#define HIDn 64
#define UPn 256
#define Rn  32
#define GHn 8

// ---- device scratch (no runtime allocation allowed) ----
__device__ float  g_mu[Bsz * Cch];
__device__ float  g_sd[Bsz * Cch];
__device__ float  g_rw[Bsz * En];
__device__ float4 g_weff4[(Bsz * OCn * Cch * 9) / 4];  // 18.9 MB mixed weights

// ============================================================
// Kernel 1: per-(b,c) mean / population-std over 64x64 spatial
// ============================================================
__global__ void stats_kernel(const float* __restrict__ x) {
    int bc = blockIdx.x;  // b*C + c
    const float4* p = (const float4*)(x + (size_t)bc * 4096);
    float s = 0.f, s2 = 0.f;
    for (int i = threadIdx.x; i < 1024; i += 256) {
        float4 v = p[i];
        s  += v.x + v.y + v.z + v.w;
        s2 += v.x * v.x + v.y * v.y + v.z * v.z + v.w * v.w;
    }
    __shared__ float sh[256], sh2[256];
    sh[threadIdx.x] = s; sh2[threadIdx.x] = s2;
    __syncthreads();
    for (int st = 128; st > 0; st >>= 1) {
        if (threadIdx.x < st) {
            sh[threadIdx.x]  += sh[threadIdx.x + st];
            sh2[threadIdx.x] += sh2[threadIdx.x + st];
        }
        __syncthreads();
    }
    if (threadIdx.x == 0) {
        float mu  = sh[0] * (1.f / 4096.f);
        float var = sh2[0] * (1.f / 4096.f) - mu * mu;
        g_mu[bc] = mu;
        g_sd[bc] = sqrtf(fmaxf(var, 0.f)) + 1e-6f;
    }
}

// ============================================================
// Kernel 2: router MLP chain + softmax -> g_rw[B][E]
// One block per batch, 256 threads.
// ============================================================
__global__ void router_kernel(
    const float* __restrict__ time_emb,
    const float* __restrict__ W_q,  const float* __restrict__ W_k,  const float* __restrict__ W_v,
    const float* __restrict__ W_g,  const float* __restrict__ b_g,
    const float* __restrict__ W_a1, const float* __restrict__ b_a1, const float* __restrict__ W_a2,
    const float* __restrict__ W_b1, const float* __restrict__ b_b1, const float* __restrict__ W_b2,
    const float* __restrict__ W_d,  const float* __restrict__ W_out)
{
    int b   = blockIdx.x;
    int tid = threadIdx.x;
    __shared__ float te[Tn], stats[2 * Cch], xh[HIDn], a1v[GHn], b1v[GHn],
                     tv[Rn], hv[UPn], xm[HIDn], lg[En];

    te[tid] = time_emb[b * Tn + tid];
    if (tid < Cch) {
        stats[tid]       = g_mu[b * Cch + tid];
        stats[Cch + tid] = g_sd[b * Cch + tid];
    }
    __syncthreads();

    // q/k/v -> xh = v * sigmoid(q*k)
    if (tid < HIDn) {
        float q = 0.f, k = 0.f, v = 0.f;
        for (int j = 0; j < Tn; j++) q += W_q[tid * Tn + j] * te[j];
        for (int j = 0; j < 2 * Cch; j++) {
            float s = stats[j];
            k += W_k[tid * 2 * Cch + j] * s;
            v += W_v[tid * 2 * Cch + j] * s;
        }
        float g = q * k;
        xh[tid] = v / (1.f + expf(-g));
    }
    __syncthreads();

    // a1 = silu(W_a1@xh + b_a1); b1 = silu(W_b1@xh + b_b1)
    if (tid < GHn) {
        float sa = b_a1[tid], sb = b_b1[tid];
        for (int i = 0; i < HIDn; i++) {
            sa += W_a1[tid * HIDn + i] * xh[i];
            sb += W_b1[tid * HIDn + i] * xh[i];
        }
        a1v[tid] = sa / (1.f + expf(-sa));
        b1v[tid] = sb / (1.f + expf(-sb));
    }
    __syncthreads();

    // t[r] = sum_i xh[i] * A[i][r],  A[i][r] = W_a2[(i*R+r),:] . a1
    if (tid < Rn) {
        float acc = 0.f;
        for (int i = 0; i < HIDn; i++) {
            const float* wrow = W_a2 + (size_t)(i * Rn + tid) * GHn;
            float ai = 0.f;
            #pragma unroll
            for (int g = 0; g < GHn; g++) ai += wrow[g] * a1v[g];
            acc += xh[i] * ai;
        }
        tv[tid] = acc;
    }
    __syncthreads();

    // gate + dyn -> h = silu(gate)*dyn   (all 256 threads, o = tid)
    {
        float gate = b_g[tid];
        for (int i = 0; i < HIDn; i++) gate += W_g[tid * HIDn + i] * xh[i];
        float dyn = 0.f;
        for (int r = 0; r < Rn; r++) {
            const float* wrow = W_b2 + (size_t)(r * UPn + tid) * GHn;
            float bm = 0.f;
            #pragma unroll
            for (int g = 0; g < GHn; g++) bm += wrow[g] * b1v[g];
            dyn += tv[r] * bm;
        }
        hv[tid] = (gate / (1.f + expf(-gate))) * dyn;
    }
    __syncthreads();

    // xm = xh + W_d @ h
    if (tid < HIDn) {
        float m = xh[tid];
        for (int o = 0; o < UPn; o++) m += W_d[tid * UPn + o] * hv[o];
        xm[tid] = m;
    }
    __syncthreads();

    if (tid < En) {
        float l = 0.f;
        for (int i = 0; i < HIDn; i++) l += W_out[tid * HIDn + i] * xm[i];
        lg[tid] = l;
    }
    __syncthreads();

    if (tid == 0) {
        float mx = lg[0];
        for (int e = 1; e < En; e++) mx = fmaxf(mx, lg[e]);
        float ex[En]; float s = 0.f;
        for (int e = 0; e < En; e++) { ex[e] = expf(lg[e] - mx); s += ex[e]; }
        float inv = 1.f / s;
        for (int e = 0; e < En; e++) g_rw[b * En + e] = ex[e] * inv;
    }
}

// ============================================================
// Kernel 3: weff[b] = sum_e rw[b,e] * expert_w[e]  (float4)
// ============================================================
__global__ void mix_kernel(const float* __restrict__ expert_w) {
    int idx = blockIdx.x * 256 + threadIdx.x;          // float4 index
    const int per_b = (OCn * Cch * 9) / 4;             // 36864 float4 per batch/expert
    int b  = idx / per_b;
    int r4 = idx - b * per_b;
    const float4* src = (const float4*)expert_w;
    float4 acc = make_float4(0.f, 0.f, 0.f, 0.f);
    #pragma unroll
    for (int e = 0; e < En; e++) {
        float w  = g_rw[b * En + e];
        float4 v = __ldg(&src[(size_t)e * per_b + r4]);
        acc.x += w * v.x; acc.y += w * v.y; acc.z += w * v.z; acc.w += w * v.w;
    }
    g_weff4[idx] = acc;
}

// ============================================================
// Kernel 4: per-batch 3x3 conv with mixed weights
// CTA: (batch, 64 OCs, 8x32 spatial tile). 256 threads.
// Thread: 8 OC x 8 rows register tile (col = tx fixed).
// ============================================================
#define TH  8
#define TW  32
#define OCT 64
#define CC  8

__global__ void __launch_bounds__(256, 2) conv_kernel(const float* __restrict__ x,
                                                      float* __restrict__ out)
{
    __shared__ float sx[CC][TH + 2][TW + 4];  // [8][10][36]
    __shared__ float sw[CC][9][OCT + 1];      // [8][9][65] (pad kills k-stride conflicts)

    int b     = blockIdx.z;
    int oc0   = blockIdx.y * OCT;
    int tileY = (blockIdx.x >> 1) * TH;
    int tileX = (blockIdx.x & 1) * TW;
    int tid   = threadIdx.x;
    int ty    = tid >> 5;   // 0..7 : oc group
    int tx    = tid & 31;   // 0..31: column within tile

    float acc[8][8];
    #pragma unroll
    for (int j = 0; j < 8; j++)
        #pragma unroll
        for (int p = 0; p < 8; p++) acc[j][p] = 0.f;

    const float* xb = x + (size_t)b * Cch * Hh * Ww;
    const float* wb = (const float*)g_weff4 +
                      (size_t)b * OCn * Cch * 9 + (size_t)oc0 * Cch * 9;

    for (int cb = 0; cb < Cch / CC; cb++) {
        // ---- load x tile (with halo, zero-padded) : 8*10*34 = 2720 elems
        for (int i = tid; i < CC * 10 * 34; i += 256) {
            int cl  = i / 340;
            int rem = i - cl * 340;
            int r   = rem / 34;
            int cc  = rem - r * 34;
            int gy  = tileY + r - 1;
            int gx  = tileX + cc - 1;
            float v = 0.f;
            if ((unsigned)gy < 64u && (unsigned)gx < 64u)
                v = xb[((size_t)(cb * CC + cl) * 64 + gy) * 64 + gx];
            sx[cl][r][cc] = v;
        }
        // ---- load weight chunk : 64oc * 8c * 9 = 4608 elems
        for (int i = tid; i < OCT * CC * 9; i += 256) {
            int oc  = i / (CC * 9);
            int rem = i - oc * CC * 9;
            int cl  = rem / 9;
            int k   = rem - cl * 9;
            sw[cl][k][oc] = wb[(size_t)oc * Cch * 9 + (size_t)(cb * CC + cl) * 9 + k];
        }
        __syncthreads();

        #pragma unroll
        for (int cl = 0; cl < CC; cl++) {
            #pragma unroll
            for (int kh = 0; kh < 3; kh++) {
                #pragma unroll
                for (int kw = 0; kw < 3; kw++) {
                    float wv[8], xv[8];
                    #pragma unroll
                    for (int j = 0; j < 8; j++) wv[j] = sw[cl][kh * 3 + kw][ty + 8 * j];
                    #pragma unroll
                    for (int p = 0; p < 8; p++) xv[p] = sx[cl][p + kh][tx + kw];
                    #pragma unroll
                    for (int j = 0; j < 8; j++)
                        #pragma unroll
                        for (int p = 0; p < 8; p++)
                            acc[j][p] = fmaf(wv[j], xv[p], acc[j][p]);
                }
            }
        }
        __syncthreads();
    }

    // ---- store (fully coalesced: 32 consecutive cols per warp)
    #pragma unroll
    for (int j = 0; j < 8; j++) {
        int oc = oc0 + ty + 8 * j;
        #pragma unroll
        for (int p = 0; p < 8; p++) {
            out[(((size_t)b * OCn + oc) * 64 + tileY + p) * 64 + tileX + tx] = acc[j][p];
        }
    }
}

// ============================================================
extern "C" void kernel_launch(void* const* d_in, const int* in_sizes, int n_in,
                              void* d_out, int out_size)
{
    const float* x        = (const float*)d_in[0];
    const float* time_emb = (const float*)d_in[1];
    const float* expert_w = (const float*)d_in[2];
    const float* W_q      = (const float*)d_in[3];
    const float* W_k      = (const float*)d_in[4];
    const float* W_v      = (const float*)d_in[5];
    const float* W_g      = (const float*)d_in[6];
    const float* b_g      = (const float*)d_in[7];
    const float* W_a1     = (const float*)d_in[8];
    const float* b_a1     = (const float*)d_in[9];
    const float* W_a2     = (const float*)d_in[10];
    const float* W_b1     = (const float*)d_in[11];
    const float* b_b1     = (const float*)d_in[12];
    const float* W_b2     = (const float*)d_in[13];
    const float* W_d      = (const float*)d_in[14];
    const float* W_out    = (const float*)d_in[15];
    float* out = (float*)d_out;

    stats_kernel<<<Bsz * Cch, 256>>>(x);
    router_kernel<<<Bsz, 256>>>(time_emb, W_q, W_k, W_v, W_g, b_g,
                                W_a1, b_a1, W_a2, W_b1, b_b1, W_b2, W_d, W_out);
    mix_kernel<<<(Bsz * OCn * Cch * 9) / 4 / 256, 256>>>(expert_w);
    conv_kernel<<<dim3(16, 2, Bsz), 256>>>(x, out);
}

// round 2
// speedup vs baseline: 1.3204x; 1.3204x over previous
#include <cuda_runtime.h>
#include <math.h>

#define Bsz 32
#define Cch 128
#define Hh  64
#define Ww  64
#define OCn 128
#define En  8
#define Tn  256
#define HIDn 64
#define UPn 256
#define Rn  32
#define GHn 8

// ---- device scratch (no runtime allocation allowed) ----
__device__ float  g_mu[Bsz * Cch];
__device__ float  g_sd[Bsz * Cch];
__device__ float  g_rw[Bsz * En];
__device__ float4 g_weff4[(Bsz * OCn * Cch * 9) / 4];  // 18.9 MB mixed weights

// ============================================================
// Kernel 1: per-(b,c) mean / population-std over 64x64 spatial
// ============================================================
__global__ void stats_kernel(const float* __restrict__ x) {
    int bc = blockIdx.x;  // b*C + c
    const float4* p = (const float4*)(x + (size_t)bc * 4096);
    float s = 0.f, s2 = 0.f;
    for (int i = threadIdx.x; i < 1024; i += 256) {
        float4 v = p[i];
        s  += v.x + v.y + v.z + v.w;
        s2 += v.x * v.x + v.y * v.y + v.z * v.z + v.w * v.w;
    }
    __shared__ float sh[256], sh2[256];
    sh[threadIdx.x] = s; sh2[threadIdx.x] = s2;
    __syncthreads();
    for (int st = 128; st > 0; st >>= 1) {
        if (threadIdx.x < st) {
            sh[threadIdx.x]  += sh[threadIdx.x + st];
            sh2[threadIdx.x] += sh2[threadIdx.x + st];
        }
        __syncthreads();
    }
    if (threadIdx.x == 0) {
        float mu  = sh[0] * (1.f / 4096.f);
        float var = sh2[0] * (1.f / 4096.f) - mu * mu;
        g_mu[bc] = mu;
        g_sd[bc] = sqrtf(fmaxf(var, 0.f)) + 1e-6f;
    }
}

// ============================================================
// Kernel 2: router MLP chain + softmax -> g_rw[B][E]
// ============================================================
__global__ void router_kernel(
    const float* __restrict__ time_emb,
    const float* __restrict__ W_q,  const float* __restrict__ W_k,  const float* __restrict__ W_v,
    const float* __restrict__ W_g,  const float* __restrict__ b_g,
    const float* __restrict__ W_a1, const float* __restrict__ b_a1, const float* __restrict__ W_a2,
    const float* __restrict__ W_b1, const float* __restrict__ b_b1, const float* __restrict__ W_b2,
    const float* __restrict__ W_d,  const float* __restrict__ W_out)
{
    int b   = blockIdx.x;
    int tid = threadIdx.x;
    __shared__ float te[Tn], stats[2 * Cch], xh[HIDn], a1v[GHn], b1v[GHn],
                     tv[Rn], hv[UPn], xm[HIDn], lg[En];

    te[tid] = time_emb[b * Tn + tid];
    if (tid < Cch) {
        stats[tid]       = g_mu[b * Cch + tid];
        stats[Cch + tid] = g_sd[b * Cch + tid];
    }
    __syncthreads();

    if (tid < HIDn) {
        float q = 0.f, k = 0.f, v = 0.f;
        for (int j = 0; j < Tn; j++) q += W_q[tid * Tn + j] * te[j];
        for (int j = 0; j < 2 * Cch; j++) {
            float s = stats[j];
            k += W_k[tid * 2 * Cch + j] * s;
            v += W_v[tid * 2 * Cch + j] * s;
        }
        float g = q * k;
        xh[tid] = v / (1.f + expf(-g));
    }
    __syncthreads();

    if (tid < GHn) {
        float sa = b_a1[tid], sb = b_b1[tid];
        for (int i = 0; i < HIDn; i++) {
            sa += W_a1[tid * HIDn + i] * xh[i];
            sb += W_b1[tid * HIDn + i] * xh[i];
        }
        a1v[tid] = sa / (1.f + expf(-sa));
        b1v[tid] = sb / (1.f + expf(-sb));
    }
    __syncthreads();

    if (tid < Rn) {
        float acc = 0.f;
        for (int i = 0; i < HIDn; i++) {
            const float* wrow = W_a2 + (size_t)(i * Rn + tid) * GHn;
            float ai = 0.f;
            #pragma unroll
            for (int g = 0; g < GHn; g++) ai += wrow[g] * a1v[g];
            acc += xh[i] * ai;
        }
        tv[tid] = acc;
    }
    __syncthreads();

    {
        float gate = b_g[tid];
        for (int i = 0; i < HIDn; i++) gate += W_g[tid * HIDn + i] * xh[i];
        float dyn = 0.f;
        for (int r = 0; r < Rn; r++) {
            const float* wrow = W_b2 + (size_t)(r * UPn + tid) * GHn;
            float bm = 0.f;
            #pragma unroll
            for (int g = 0; g < GHn; g++) bm += wrow[g] * b1v[g];
            dyn += tv[r] * bm;
        }
        hv[tid] = (gate / (1.f + expf(-gate))) * dyn;
    }
    __syncthreads();

    if (tid < HIDn) {
        float m = xh[tid];
        for (int o = 0; o < UPn; o++) m += W_d[tid * UPn + o] * hv[o];
        xm[tid] = m;
    }
    __syncthreads();

    if (tid < En) {
        float l = 0.f;
        for (int i = 0; i < HIDn; i++) l += W_out[tid * HIDn + i] * xm[i];
        lg[tid] = l;
    }
    __syncthreads();

    if (tid == 0) {
        float mx = lg[0];
        for (int e = 1; e < En; e++) mx = fmaxf(mx, lg[e]);
        float ex[En]; float s = 0.f;
        for (int e = 0; e < En; e++) { ex[e] = expf(lg[e] - mx); s += ex[e]; }
        float inv = 1.f / s;
        for (int e = 0; e < En; e++) g_rw[b * En + e] = ex[e] * inv;
    }
}

// ============================================================
// Kernel 3: weff[b] = sum_e rw[b,e] * expert_w[e]  (float4)
// ============================================================
__global__ void mix_kernel(const float* __restrict__ expert_w) {
    int idx = blockIdx.x * 256 + threadIdx.x;
    const int per_b = (OCn * Cch * 9) / 4;
    int b  = idx / per_b;
    int r4 = idx - b * per_b;
    const float4* src = (const float4*)expert_w;
    float4 acc = make_float4(0.f, 0.f, 0.f, 0.f);
    #pragma unroll
    for (int e = 0; e < En; e++) {
        float w  = g_rw[b * En + e];
        float4 v = __ldg(&src[(size_t)e * per_b + r4]);
        acc.x += w * v.x; acc.y += w * v.y; acc.z += w * v.z; acc.w += w * v.w;
    }
    g_weff4[idx] = acc;
}

// ============================================================
// Kernel 4: per-batch 3x3 conv using packed FFMA2 (fma.rn.f32x2)
// CTA: (batch, 64 OCs, 8x32 spatial tile). 256 threads.
// Thread: 8 consecutive OCs (4 f32x2 pairs) x 8 rows.
// ============================================================
#define TH  8
#define TW  32
#define OCT 64
#define CC  8

__device__ __forceinline__ unsigned long long f32x2_dup(float v) {
    unsigned long long r;
    asm("mov.b64 %0, {%1, %1};" : "=l"(r) : "f"(v));
    return r;
}
__device__ __forceinline__ void ffma2(unsigned long long& acc,
                                      unsigned long long a,
                                      unsigned long long b) {
    asm("fma.rn.f32x2 %0, %1, %2, %0;" : "+l"(acc) : "l"(a), "l"(b));
}
__device__ __forceinline__ void f32x2_unpack(unsigned long long v, float& lo, float& hi) {
    asm("mov.b64 {%0, %1}, %2;" : "=f"(lo), "=f"(hi) : "l"(v));
}

__global__ void __launch_bounds__(256, 2) conv_kernel(const float* __restrict__ x,
                                                      float* __restrict__ out)
{
    __shared__ float sx[CC][TH + 2][TW + 4];  // [8][10][36]
    __shared__ float sw[CC][9][OCT + 2];      // [8][9][66] rows 8B-aligned (264B pitch)

    int b     = blockIdx.z;
    int oc0   = blockIdx.y * OCT;
    int tileY = (blockIdx.x >> 1) * TH;
    int tileX = (blockIdx.x & 1) * TW;
    int tid   = threadIdx.x;
    int ty    = tid >> 5;   // 0..7 : this thread owns ocs [oc0 + ty*8, +8)
    int tx    = tid & 31;   // 0..31: column within tile

    unsigned long long acc2[4][8];  // [oc-pair][pixel-row]
    #pragma unroll
    for (int jp = 0; jp < 4; jp++)
        #pragma unroll
        for (int p = 0; p < 8; p++) acc2[jp][p] = 0ull;

    const float* xb = x + (size_t)b * Cch * Hh * Ww;
    const float* wb = (const float*)g_weff4 +
                      (size_t)b * OCn * Cch * 9 + (size_t)oc0 * Cch * 9;

    for (int cb = 0; cb < Cch / CC; cb++) {
        // ---- load x tile (with halo, zero-padded)
        for (int i = tid; i < CC * 10 * 34; i += 256) {
            int cl  = i / 340;
            int rem = i - cl * 340;
            int r   = rem / 34;
            int cc  = rem - r * 34;
            int gy  = tileY + r - 1;
            int gx  = tileX + cc - 1;
            float v = 0.f;
            if ((unsigned)gy < 64u && (unsigned)gx < 64u)
                v = xb[((size_t)(cb * CC + cl) * 64 + gy) * 64 + gx];
            sx[cl][r][cc] = v;
        }
        // ---- load weight chunk : 64oc * 8c * 9
        for (int i = tid; i < OCT * CC * 9; i += 256) {
            int oc  = i / (CC * 9);
            int rem = i - oc * CC * 9;
            int cl  = rem / 9;
            int k   = rem - cl * 9;
            sw[cl][k][oc] = wb[(size_t)oc * Cch * 9 + (size_t)(cb * CC + cl) * 9 + k];
        }
        __syncthreads();

        #pragma unroll
        for (int cl = 0; cl < CC; cl++) {
            #pragma unroll
            for (int kw = 0; kw < 3; kw++) {
                // load 10-row x column once, duplicate into f32x2
                unsigned long long xd[10];
                #pragma unroll
                for (int r = 0; r < 10; r++)
                    xd[r] = f32x2_dup(sx[cl][r][tx + kw]);
                #pragma unroll
                for (int kh = 0; kh < 3; kh++) {
                    int k = kh * 3 + kw;
                    #pragma unroll
                    for (int jp = 0; jp < 4; jp++) {
                        // two consecutive oc weights in one 64-bit shared load
                        unsigned long long w2 =
                            *(const unsigned long long*)&sw[cl][k][ty * 8 + jp * 2];
                        #pragma unroll
                        for (int p = 0; p < 8; p++)
                            ffma2(acc2[jp][p], w2, xd[p + kh]);
                    }
                }
            }
        }
        __syncthreads();
    }

    // ---- store (coalesced: 32 consecutive cols per warp)
    #pragma unroll
    for (int jp = 0; jp < 4; jp++) {
        int ocA = oc0 + ty * 8 + jp * 2;
        #pragma unroll
        for (int p = 0; p < 8; p++) {
            float lo, hi;
            f32x2_unpack(acc2[jp][p], lo, hi);
            size_t base = (((size_t)b * OCn + ocA) * 64 + tileY + p) * 64 + tileX + tx;
            out[base]            = lo;
            out[base + 64 * 64]  = hi;
        }
    }
}

// ============================================================
extern "C" void kernel_launch(void* const* d_in, const int* in_sizes, int n_in,
                              void* d_out, int out_size)
{
    const float* x        = (const float*)d_in[0];
    const float* time_emb = (const float*)d_in[1];
    const float* expert_w = (const float*)d_in[2];
    const float* W_q      = (const float*)d_in[3];
    const float* W_k      = (const float*)d_in[4];
    const float* W_v      = (const float*)d_in[5];
    const float* W_g      = (const float*)d_in[6];
    const float* b_g      = (const float*)d_in[7];
    const float* W_a1     = (const float*)d_in[8];
    const float* b_a1     = (const float*)d_in[9];
    const float* W_a2     = (const float*)d_in[10];
    const float* W_b1     = (const float*)d_in[11];
    const float* b_b1     = (const float*)d_in[12];
    const float* W_b2     = (const float*)d_in[13];
    const float* W_d      = (const float*)d_in[14];
    const float* W_out    = (const float*)d_in[15];
    float* out = (float*)d_out;

    stats_kernel<<<Bsz * Cch, 256>>>(x);
    router_kernel<<<Bsz, 256>>>(time_emb, W_q, W_k, W_v, W_g, b_g,
                                W_a1, b_a1, W_a2, W_b1, b_b1, W_b2, W_d, W_out);
    mix_kernel<<<(Bsz * OCn * Cch * 9) / 4 / 256, 256>>>(expert_w);
    conv_kernel<<<dim3(16, 2, Bsz), 256>>>(x, out);
}